// round 13
// baseline (speedup 1.0000x reference)
#include <cuda_runtime.h>
#include <cuda_fp16.h>
#include <cstdint>
#include <cstddef>

#define IN_F     4096
#define OUT_F    11008
#define M_TOKENS 4096

#define BM 128
#define BN 128
#define BK 64
#define KITERS (IN_F / BK)

#define DQ_BLOCKS 44032     // 45,088,768 weight elems / 4 / 256
#define CX_BLOCKS 16384     // 16,777,216 x elems / 4 / 256

// -------- scratch (device globals: allocation-free) --------
__device__ __half g_W[(size_t)OUT_F * IN_F];    // dequantized weights fp16 [O, I]
__device__ __half g_X[(size_t)M_TOKENS * IN_F]; // activations fp16 [M, I]

// ---------------- PTX helpers (base-target features only) ----------------
__device__ __forceinline__ uint32_t smem_u32(const void* p) {
    uint32_t a;
    asm("{ .reg .u64 t; cvta.to.shared.u64 t, %1; cvt.u32.u64 %0, t; }" : "=r"(a) : "l"(p));
    return a;
}
__device__ __forceinline__ void cp16(uint32_t dst, const void* src) {
    asm volatile("cp.async.cg.shared.global [%0], [%1], 16;" :: "r"(dst), "l"(src) : "memory");
}
__device__ __forceinline__ void cp_commit() {
    asm volatile("cp.async.commit_group;" ::: "memory");
}
template <int N>
__device__ __forceinline__ void cp_wait() {
    asm volatile("cp.async.wait_group %0;" :: "n"(N) : "memory");
}
__device__ __forceinline__ void ldsm_x4(uint32_t& r0, uint32_t& r1, uint32_t& r2, uint32_t& r3,
                                        uint32_t addr) {
    asm volatile("ldmatrix.sync.aligned.m8n8.x4.shared.b16 {%0,%1,%2,%3}, [%4];"
                 : "=r"(r0), "=r"(r1), "=r"(r2), "=r"(r3) : "r"(addr));
}
__device__ __forceinline__ void mma16816(float* d, const uint32_t* a, const uint32_t* b) {
    asm volatile(
        "mma.sync.aligned.m16n8k16.row.col.f32.f16.f16.f32 "
        "{%0,%1,%2,%3}, {%4,%5,%6,%7}, {%8,%9}, {%0,%1,%2,%3};"
        : "+f"(d[0]), "+f"(d[1]), "+f"(d[2]), "+f"(d[3])
        : "r"(a[0]), "r"(a[1]), "r"(a[2]), "r"(a[3]), "r"(b[0]), "r"(b[1]));
}
__device__ __forceinline__ uint32_t sw128(uint32_t off) {
    return off ^ ((off >> 3) & 0x70);
}

// ---------------- fused prepass: dequant W + convert x (one launch) ----------------
__global__ void __launch_bounds__(256) prepass_kernel(const int* __restrict__ q,
                                                      const float* __restrict__ sc,
                                                      const int* __restrict__ mask,
                                                      const float* __restrict__ x) {
    if (blockIdx.x < DQ_BLOCKS) {
        size_t t = (size_t)blockIdx.x * 256 + threadIdx.x;   // 4 weight elements
        int4 qv = reinterpret_cast<const int4*>(q)[t];
        int4 mv = reinterpret_cast<const int4*>(mask)[t];
        float s = sc[(t * 4) >> 6];
        const float k = 2.0f / 7.0f;
        float w0 = mv.x ? 0.f : ((float)qv.x * k - 1.0f) * s;
        float w1 = mv.y ? 0.f : ((float)qv.y * k - 1.0f) * s;
        float w2 = mv.z ? 0.f : ((float)qv.z * k - 1.0f) * s;
        float w3 = mv.w ? 0.f : ((float)qv.w * k - 1.0f) * s;
        __half2 p0 = __floats2half2_rn(w0, w1);
        __half2 p1 = __floats2half2_rn(w2, w3);
        uint2 st;
        st.x = *reinterpret_cast<uint32_t*>(&p0);
        st.y = *reinterpret_cast<uint32_t*>(&p1);
        reinterpret_cast<uint2*>(g_W)[t] = st;
    } else {
        size_t t = (size_t)(blockIdx.x - DQ_BLOCKS) * 256 + threadIdx.x;  // 4 x elements
        float4 v = reinterpret_cast<const float4*>(x)[t];
        __half2 p0 = __floats2half2_rn(v.x, v.y);
        __half2 p1 = __floats2half2_rn(v.z, v.w);
        uint2 st;
        st.x = *reinterpret_cast<uint32_t*>(&p0);
        st.y = *reinterpret_cast<uint32_t*>(&p1);
        reinterpret_cast<uint2*>(g_X)[t] = st;
    }
}

// ---------------- GEMM: mma.sync fp16, 2-stage double buffer, 128 thr, 3 CTA/SM ----------------
// SMEM: A slot0 @0, A slot1 @16K, B slot0 @32K, B slot1 @48K -> 64KB total
#define SLOT_XOR   16384u
#define SMEM_B_OFF 32768u
#define SMEM_TOTAL 65536

__global__ void __launch_bounds__(128, 3) gemm_kernel(const float* __restrict__ bias,
                                                      float* __restrict__ out) {
    extern __shared__ __align__(1024) char smem[];
    uint32_t sb = smem_u32(smem);
    const int tid = threadIdx.x;
    const int lane = tid & 31;
    const int wid = tid >> 5;            // 4 warps: 2(M) x 2(N), warp tile 64x64
    const int wm = (wid & 1) * 64;
    const int wn = (wid >> 1) * 64;

    const int m_base = blockIdx.x * BM;  // fast-varying -> wave shares B in L2
    const int n_base = blockIdx.y * BN;

    // ---- producer per-thread invariants ----
    const int prow = tid >> 3;
    const int pkc  = tid & 7;
    const __half* pA = g_X + (size_t)(m_base + prow) * IN_F + pkc * 8;
    const __half* pB = g_W + (size_t)(n_base + prow) * IN_F + pkc * 8;
    const uint32_t sA0 = sw128((uint32_t)(prow * 128 + pkc * 16));

    // ---- prologue: load stage 0 into slot 0 ----
    {
        uint32_t da = sb + sA0;
        uint32_t db = sb + SMEM_B_OFF + sA0;
#pragma unroll
        for (int i = 0; i < 8; ++i) cp16(da + i * 2048, pA + (size_t)(i * 16) * IN_F);
#pragma unroll
        for (int i = 0; i < 8; ++i) cp16(db + i * 2048, pB + (size_t)(i * 16) * IN_F);
        cp_commit();
    }
    pA += BK;
    pB += BK;

    float acc[4][8][4];
#pragma unroll
    for (int mi = 0; mi < 4; ++mi)
#pragma unroll
        for (int ni = 0; ni < 8; ++ni)
#pragma unroll
            for (int r = 0; r < 4; ++r) acc[mi][ni][r] = 0.0f;

    // ---- consumer ldsm invariants: sw(R,C) = R*128 + ((C ^ (R&7))*16) ----
    const int lrow = lane & 15;
    const int lcol = lane >> 4;
    uint32_t aRow[4], aXor[4], bRow[4], bXor[4];
#pragma unroll
    for (int mi = 0; mi < 4; ++mi) {
        int r = wm + mi * 16 + lrow;
        aRow[mi] = (uint32_t)(r * 128);
        aXor[mi] = (uint32_t)(r & 7);
    }
#pragma unroll
    for (int nj = 0; nj < 4; ++nj) {
        int r = wn + nj * 16 + lrow;
        bRow[nj] = (uint32_t)(r * 128);
        bXor[nj] = (uint32_t)(r & 7);
    }

    uint32_t off = 0;   // read slot offset; write slot = off ^ SLOT_XOR

    // ---- main loop: wait -> sync -> produce(other slot) -> commit -> consume ----
    for (int k = 0; k < KITERS; ++k) {
        cp_wait<0>();              // all pending groups done => stage k resident (own copies)
        __syncthreads();           // visibility of all threads' copies + WAR on refill slot

        if (k + 1 < KITERS) {
            uint32_t da = sb + (off ^ SLOT_XOR) + sA0;
            uint32_t db = sb + SMEM_B_OFF + (off ^ SLOT_XOR) + sA0;
#pragma unroll
            for (int i = 0; i < 8; ++i) cp16(da + i * 2048, pA + (size_t)(i * 16) * IN_F);
#pragma unroll
            for (int i = 0; i < 8; ++i) cp16(db + i * 2048, pB + (size_t)(i * 16) * IN_F);
            pA += BK;
            pB += BK;
        }
        cp_commit();               // uniform group accounting

        const uint32_t abaseR = sb + off;
        const uint32_t bbaseR = sb + SMEM_B_OFF + off;

#pragma unroll
        for (int ks = 0; ks < 4; ++ks) {   // 4 x k16 per BK=64
            const uint32_t cIdx = (uint32_t)(ks * 2 + lcol);
            uint32_t a[4][4];
            uint32_t b[8][2];
#pragma unroll
            for (int mi = 0; mi < 4; ++mi) {
                uint32_t addr = abaseR + aRow[mi] + ((cIdx ^ aXor[mi]) << 4);
                ldsm_x4(a[mi][0], a[mi][1], a[mi][2], a[mi][3], addr);
            }
#pragma unroll
            for (int nj = 0; nj < 4; ++nj) {
                uint32_t addr = bbaseR + bRow[nj] + ((cIdx ^ bXor[nj]) << 4);
                uint32_t q0, q1, q2, q3;
                ldsm_x4(q0, q1, q2, q3, addr);
                b[2 * nj + 0][0] = q0; b[2 * nj + 0][1] = q2;
                b[2 * nj + 1][0] = q1; b[2 * nj + 1][1] = q3;
            }
#pragma unroll
            for (int mi = 0; mi < 4; ++mi)
#pragma unroll
                for (int ni = 0; ni < 8; ++ni)
                    mma16816(acc[mi][ni], a[mi], b[ni]);
        }

        off ^= SLOT_XOR;
    }

    // ---- epilogue ----
    const int gid = lane >> 2;
    const int tq  = lane & 3;
    float2 bv[8];
#pragma unroll
    for (int ni = 0; ni < 8; ++ni) {
        int n = n_base + wn + ni * 8 + 2 * tq;
        bv[ni] = *reinterpret_cast<const float2*>(bias + n);
    }
#pragma unroll
    for (int mi = 0; mi < 4; ++mi) {
        int m0 = m_base + wm + mi * 16 + gid;
#pragma unroll
        for (int ni = 0; ni < 8; ++ni) {
            int n = n_base + wn + ni * 8 + 2 * tq;
            float2 v0 = make_float2(acc[mi][ni][0] + bv[ni].x, acc[mi][ni][1] + bv[ni].y);
            float2 v1 = make_float2(acc[mi][ni][2] + bv[ni].x, acc[mi][ni][3] + bv[ni].y);
            *reinterpret_cast<float2*>(out + (size_t)m0 * OUT_F + n) = v0;
            *reinterpret_cast<float2*>(out + (size_t)(m0 + 8) * OUT_F + n) = v1;
        }
    }
}

// ---------------- launch ----------------
extern "C" void kernel_launch(void* const* d_in, const int* in_sizes, int n_in,
                              void* d_out, int out_size) {
    const float* x    = (const float*)d_in[0];
    const int*   q    = (const int*)d_in[1];
    const float* sc   = (const float*)d_in[2];
    const int*   mask = (const int*)d_in[3];
    const float* bias = (const float*)d_in[4];
    float*       out  = (float*)d_out;

    prepass_kernel<<<DQ_BLOCKS + CX_BLOCKS, 256>>>(q, sc, mask, x);

    cudaFuncSetAttribute(gemm_kernel, cudaFuncAttributeMaxDynamicSharedMemorySize, SMEM_TOTAL);
    dim3 grid(M_TOKENS / BM, OUT_F / BN);             // (32, 86)
    gemm_kernel<<<grid, 128, SMEM_TOTAL>>>(bias, out);
}

// round 14
// speedup vs baseline: 1.1027x; 1.1027x over previous
#include <cuda_runtime.h>
#include <cuda_fp16.h>
#include <cstdint>
#include <cstddef>

#define IN_F     4096
#define OUT_F    11008
#define M_TOKENS 4096

#define BM 128
#define BN 128
#define BK 64
#define NSTAGE 3
#define KITERS (IN_F / BK)

#define DQ_BLOCKS 44032     // 45,088,768 weight elems / 4 / 256
#define CX_BLOCKS 16384     // 16,777,216 x elems / 4 / 256

// -------- scratch (device globals: allocation-free) --------
__device__ __half g_W[(size_t)OUT_F * IN_F];    // dequantized weights fp16 [O, I]
__device__ __half g_X[(size_t)M_TOKENS * IN_F]; // activations fp16 [M, I]

// ---------------- PTX helpers (base-target features only) ----------------
__device__ __forceinline__ uint32_t smem_u32(const void* p) {
    uint32_t a;
    asm("{ .reg .u64 t; cvta.to.shared.u64 t, %1; cvt.u32.u64 %0, t; }" : "=r"(a) : "l"(p));
    return a;
}
__device__ __forceinline__ void cp16(uint32_t dst, const void* src) {
    asm volatile("cp.async.cg.shared.global [%0], [%1], 16;" :: "r"(dst), "l"(src) : "memory");
}
__device__ __forceinline__ void cp_commit() {
    asm volatile("cp.async.commit_group;" ::: "memory");
}
template <int N>
__device__ __forceinline__ void cp_wait() {
    asm volatile("cp.async.wait_group %0;" :: "n"(N) : "memory");
}
__device__ __forceinline__ void ldsm_x4(uint32_t& r0, uint32_t& r1, uint32_t& r2, uint32_t& r3,
                                        uint32_t addr) {
    asm volatile("ldmatrix.sync.aligned.m8n8.x4.shared.b16 {%0,%1,%2,%3}, [%4];"
                 : "=r"(r0), "=r"(r1), "=r"(r2), "=r"(r3) : "r"(addr));
}
__device__ __forceinline__ void mma16816(float* d, const uint32_t* a, const uint32_t* b) {
    asm volatile(
        "mma.sync.aligned.m16n8k16.row.col.f32.f16.f16.f32 "
        "{%0,%1,%2,%3}, {%4,%5,%6,%7}, {%8,%9}, {%0,%1,%2,%3};"
        : "+f"(d[0]), "+f"(d[1]), "+f"(d[2]), "+f"(d[3])
        : "r"(a[0]), "r"(a[1]), "r"(a[2]), "r"(a[3]), "r"(b[0]), "r"(b[1]));
}
__device__ __forceinline__ uint32_t sw128(uint32_t off) {
    return off ^ ((off >> 3) & 0x70);
}

// ---------------- fused prepass: dequant W + convert x (one launch) ----------------
__global__ void __launch_bounds__(256) prepass_kernel(const int* __restrict__ q,
                                                      const float* __restrict__ sc,
                                                      const int* __restrict__ mask,
                                                      const float* __restrict__ x) {
    if (blockIdx.x < DQ_BLOCKS) {
        size_t t = (size_t)blockIdx.x * 256 + threadIdx.x;   // 4 weight elements
        int4 qv = reinterpret_cast<const int4*>(q)[t];
        int4 mv = reinterpret_cast<const int4*>(mask)[t];
        float s = sc[(t * 4) >> 6];
        const float k = 2.0f / 7.0f;
        float w0 = mv.x ? 0.f : ((float)qv.x * k - 1.0f) * s;
        float w1 = mv.y ? 0.f : ((float)qv.y * k - 1.0f) * s;
        float w2 = mv.z ? 0.f : ((float)qv.z * k - 1.0f) * s;
        float w3 = mv.w ? 0.f : ((float)qv.w * k - 1.0f) * s;
        __half2 p0 = __floats2half2_rn(w0, w1);
        __half2 p1 = __floats2half2_rn(w2, w3);
        uint2 st;
        st.x = *reinterpret_cast<uint32_t*>(&p0);
        st.y = *reinterpret_cast<uint32_t*>(&p1);
        reinterpret_cast<uint2*>(g_W)[t] = st;
    } else {
        size_t t = (size_t)(blockIdx.x - DQ_BLOCKS) * 256 + threadIdx.x;  // 4 x elements
        float4 v = reinterpret_cast<const float4*>(x)[t];
        __half2 p0 = __floats2half2_rn(v.x, v.y);
        __half2 p1 = __floats2half2_rn(v.z, v.w);
        uint2 st;
        st.x = *reinterpret_cast<uint32_t*>(&p0);
        st.y = *reinterpret_cast<uint32_t*>(&p1);
        reinterpret_cast<uint2*>(g_X)[t] = st;
    }
}

// ---------------- GEMM: mma.sync fp16, 3-stage pipeline, 128 thr, 2 CTA/SM ----------------
#define A_STAGE_BYTES (BM * BK * 2)            // 16384
#define B_STAGE_BYTES (BN * BK * 2)            // 16384
#define SMEM_B_OFF (NSTAGE * A_STAGE_BYTES)    // 49152
#define SMEM_TOTAL (SMEM_B_OFF + NSTAGE * B_STAGE_BYTES)  // 98304 (96KB)

__global__ void __launch_bounds__(128, 2) gemm_kernel(const float* __restrict__ bias,
                                                      float* __restrict__ out) {
    extern __shared__ __align__(1024) char smem[];
    uint32_t sb = smem_u32(smem);
    const int tid = threadIdx.x;
    const int lane = tid & 31;
    const int wid = tid >> 5;            // 4 warps: 2(M) x 2(N), warp tile 64x64
    const int wm = (wid & 1) * 64;
    const int wn = (wid >> 1) * 64;

    const int m_base = blockIdx.x * BM;  // fast-varying -> wave shares B in L2
    const int n_base = blockIdx.y * BN;

    // ---- producer per-thread invariants ----
    const int prow = tid >> 3;
    const int pkc  = tid & 7;
    const __half* pA = g_X + (size_t)(m_base + prow) * IN_F + pkc * 8;
    const __half* pB = g_W + (size_t)(n_base + prow) * IN_F + pkc * 8;
    const uint32_t sA0 = sw128((uint32_t)(prow * 128 + pkc * 16));

    // ---- pipeline prologue: stages 0..1 (one commit group each) ----
#pragma unroll
    for (int s = 0; s < NSTAGE - 1; ++s) {
        uint32_t da = sb + s * A_STAGE_BYTES + sA0;
        uint32_t db = sb + SMEM_B_OFF + s * B_STAGE_BYTES + sA0;
        const __half* a = pA + s * BK;
        const __half* b = pB + s * BK;
#pragma unroll
        for (int i = 0; i < 8; ++i) cp16(da + i * 2048, a + (size_t)(i * 16) * IN_F);
#pragma unroll
        for (int i = 0; i < 8; ++i) cp16(db + i * 2048, b + (size_t)(i * 16) * IN_F);
        cp_commit();
    }
    pA += (NSTAGE - 1) * BK;
    pB += (NSTAGE - 1) * BK;

    float acc[4][8][4];
#pragma unroll
    for (int mi = 0; mi < 4; ++mi)
#pragma unroll
        for (int ni = 0; ni < 8; ++ni)
#pragma unroll
            for (int r = 0; r < 4; ++r) acc[mi][ni][r] = 0.0f;

    // ---- consumer ldsm invariants: sw(R,C) = R*128 + ((C ^ (R&7))*16) ----
    const int lrow = lane & 15;
    const int lcol = lane >> 4;
    uint32_t aRow[4], aXor[4], bRow[4], bXor[4];
#pragma unroll
    for (int mi = 0; mi < 4; ++mi) {
        int r = wm + mi * 16 + lrow;
        aRow[mi] = (uint32_t)(r * 128);
        aXor[mi] = (uint32_t)(r & 7);
    }
#pragma unroll
    for (int nj = 0; nj < 4; ++nj) {
        int r = wn + nj * 16 + lrow;
        bRow[nj] = (uint32_t)(r * 128);
        bXor[nj] = (uint32_t)(r & 7);
    }

    // wrapping slot bases (no % in loop)
    uint32_t abaseR = sb;
    uint32_t bbaseR = sb + SMEM_B_OFF;
    uint32_t abaseW = sb + (NSTAGE - 1) * A_STAGE_BYTES;
    uint32_t bbaseW = sb + SMEM_B_OFF + (NSTAGE - 1) * B_STAGE_BYTES;
    const uint32_t aEnd = sb + NSTAGE * A_STAGE_BYTES;
    const uint32_t bEnd = sb + SMEM_B_OFF + NSTAGE * B_STAGE_BYTES;

    // ---- main loop: wait(<=1 pending => stage k resident) -> sync -> consume
    //      with producer cp16 packets spread across the 4 ks-steps -> commit ----
    for (int k = 0; k < KITERS; ++k) {
        cp_wait<1>();              // stage k's group complete (own copies)
        __syncthreads();           // visibility + WAR on the slot being refilled

        const bool produce = (k + NSTAGE - 1 < KITERS);
        const uint32_t da = abaseW + sA0;
        const uint32_t db = bbaseW + sA0;

#pragma unroll
        for (int ks = 0; ks < 4; ++ks) {   // 4 x k16 per BK=64
            const uint32_t cIdx = (uint32_t)(ks * 2 + lcol);
            uint32_t a[4][4];
            uint32_t b[8][2];
#pragma unroll
            for (int mi = 0; mi < 4; ++mi) {
                uint32_t addr = abaseR + aRow[mi] + ((cIdx ^ aXor[mi]) << 4);
                ldsm_x4(a[mi][0], a[mi][1], a[mi][2], a[mi][3], addr);
            }
#pragma unroll
            for (int nj = 0; nj < 4; ++nj) {
                uint32_t addr = bbaseR + bRow[nj] + ((cIdx ^ bXor[nj]) << 4);
                uint32_t q0, q1, q2, q3;
                ldsm_x4(q0, q1, q2, q3, addr);
                b[2 * nj + 0][0] = q0; b[2 * nj + 0][1] = q2;
                b[2 * nj + 1][0] = q1; b[2 * nj + 1][1] = q3;
            }
            // producer packet: 4 cp16 issued between ldsm and mma — covers ldsm
            // latency and spreads the 16-cp16 block across the iteration.
            if (produce) {
                if (ks == 0) {
#pragma unroll
                    for (int i = 0; i < 4; ++i) cp16(da + i * 2048, pA + (size_t)(i * 16) * IN_F);
                } else if (ks == 1) {
#pragma unroll
                    for (int i = 4; i < 8; ++i) cp16(da + i * 2048, pA + (size_t)(i * 16) * IN_F);
                } else if (ks == 2) {
#pragma unroll
                    for (int i = 0; i < 4; ++i) cp16(db + i * 2048, pB + (size_t)(i * 16) * IN_F);
                } else {
#pragma unroll
                    for (int i = 4; i < 8; ++i) cp16(db + i * 2048, pB + (size_t)(i * 16) * IN_F);
                }
            }
#pragma unroll
            for (int mi = 0; mi < 4; ++mi)
#pragma unroll
                for (int ni = 0; ni < 8; ++ni)
                    mma16816(acc[mi][ni], a[mi], b[ni]);
        }

        if (produce) { pA += BK; pB += BK; }
        cp_commit();               // close this iteration's group (uniform accounting)

        // advance wrapping slot bases
        abaseR += A_STAGE_BYTES; if (abaseR == aEnd) abaseR = sb;
        bbaseR += B_STAGE_BYTES; if (bbaseR == bEnd) bbaseR = sb + SMEM_B_OFF;
        abaseW += A_STAGE_BYTES; if (abaseW == aEnd) abaseW = sb;
        bbaseW += B_STAGE_BYTES; if (bbaseW == bEnd) bbaseW = sb + SMEM_B_OFF;
    }

    // ---- epilogue ----
    const int gid = lane >> 2;
    const int tq  = lane & 3;
    float2 bv[8];
#pragma unroll
    for (int ni = 0; ni < 8; ++ni) {
        int n = n_base + wn + ni * 8 + 2 * tq;
        bv[ni] = *reinterpret_cast<const float2*>(bias + n);
    }
#pragma unroll
    for (int mi = 0; mi < 4; ++mi) {
        int m0 = m_base + wm + mi * 16 + gid;
#pragma unroll
        for (int ni = 0; ni < 8; ++ni) {
            int n = n_base + wn + ni * 8 + 2 * tq;
            float2 v0 = make_float2(acc[mi][ni][0] + bv[ni].x, acc[mi][ni][1] + bv[ni].y);
            float2 v1 = make_float2(acc[mi][ni][2] + bv[ni].x, acc[mi][ni][3] + bv[ni].y);
            *reinterpret_cast<float2*>(out + (size_t)m0 * OUT_F + n) = v0;
            *reinterpret_cast<float2*>(out + (size_t)(m0 + 8) * OUT_F + n) = v1;
        }
    }
}

// ---------------- launch ----------------
extern "C" void kernel_launch(void* const* d_in, const int* in_sizes, int n_in,
                              void* d_out, int out_size) {
    const float* x    = (const float*)d_in[0];
    const int*   q    = (const int*)d_in[1];
    const float* sc   = (const float*)d_in[2];
    const int*   mask = (const int*)d_in[3];
    const float* bias = (const float*)d_in[4];
    float*       out  = (float*)d_out;

    prepass_kernel<<<DQ_BLOCKS + CX_BLOCKS, 256>>>(q, sc, mask, x);

    cudaFuncSetAttribute(gemm_kernel, cudaFuncAttributeMaxDynamicSharedMemorySize, SMEM_TOTAL);
    dim3 grid(M_TOKENS / BM, OUT_F / BN);             // (32, 86)
    gemm_kernel<<<grid, 128, SMEM_TOTAL>>>(bias, out);
}